// round 4
// baseline (speedup 1.0000x reference)
#include <cuda_runtime.h>
#include <math.h>

// Problem dims
#define BB 2
#define HH 32
#define SS 2048
#define DD 128
#define BHN (BB*HH)

// Output layout (floats), concatenated in reference return order
#define OFF_ATTN   ((size_t)0)
#define OFF_KQ     ((size_t)16777216)
#define OFF_KSCALE ((size_t)33554432)
#define OFF_VQ     ((size_t)33562624)
#define OFF_VSCALE ((size_t)50339840)
#define OFF_KSPV   ((size_t)50470912)
#define OFF_KSPI   ((size_t)50601984)
#define OFF_VSPV   ((size_t)50733056)
#define OFF_VSPI   ((size_t)51257344)

// Scratch (device globals: no allocation allowed)
__device__ float g_qrot[BB*HH*SS*DD];
__device__ float g_krot[BB*HH*SS*DD];
__device__ float g_cos[SS*64];
__device__ float g_sin[SS*64];

// ---------------------------------------------------------------------------
// RoPE cos/sin table: must match jax f32 semantics as closely as possible.
// inv_freq = f32(1.0 / f32(10000^e)), e = 2j/128 exact in f32.
// angle = f32(pos) * inv_freq (f32 multiply). cos/sin in double on that angle.
// ---------------------------------------------------------------------------
__global__ void table_kernel() {
    int s = blockIdx.x;
    int j = threadIdx.x;
    double e = (double)(2 * j) / 128.0;
    double p = pow(10000.0, e);         // correctly rounded when cast to f32
    float pf = (float)p;
    float invf = 1.0f / pf;             // f32 division, matches reference
    float ang = __fmul_rn((float)s, invf);
    g_cos[s * 64 + j] = (float)cos((double)ang);
    g_sin[s * 64 + j] = (float)sin((double)ang);
}

// ---------------------------------------------------------------------------
// RoPE: q_rot, k_rot. No FMA contraction (match jax rounding).
// ---------------------------------------------------------------------------
__global__ void rope_kernel(const float* __restrict__ q, const float* __restrict__ k,
                            const int* __restrict__ pos_ids) {
    size_t i = (size_t)blockIdx.x * blockDim.x + threadIdx.x;
    if (i >= (size_t)BB * HH * SS * DD) return;
    int d = (int)(i & 127);
    int s = (int)((i >> 7) & 2047);
    int b = (int)(i >> 23);               // H*S*D = 2^23
    int pos = pos_ids[b * SS + s];
    int j = d & 63;
    float c  = g_cos[pos * 64 + j];
    float sn = g_sin[pos * 64 + j];

    float xq = q[i];
    float xk = k[i];
    float yq, yk;
    if (d < 64) { yq = q[i + 64]; yk = k[i + 64]; }
    else        { yq = q[i - 64]; yk = k[i - 64]; }

    float oq, ok;
    if (d < 64) {
        oq = __fsub_rn(__fmul_rn(xq, c), __fmul_rn(yq, sn));
        ok = __fsub_rn(__fmul_rn(xk, c), __fmul_rn(yk, sn));
    } else {
        oq = __fadd_rn(__fmul_rn(xq, c), __fmul_rn(yq, sn));
        ok = __fadd_rn(__fmul_rn(xk, c), __fmul_rn(yk, sn));
    }
    g_qrot[i] = oq;
    g_krot[i] = ok;
}

// ---------------------------------------------------------------------------
// Flash attention, fp32. BM=BN=64, 256 threads.
// Thread map: ty = tid/16 -> 4 query rows (ty*4+r); tx = tid%16.
// Score cols: j = tx + 16*c (conflict-free smem reads). O cols: tx*8+cc.
// ---------------------------------------------------------------------------
#define BM 64
#define BN 64
#define QT_S 66
#define KT_S 65
#define PS_S 66
#define ATTN_SMEM_FLOATS (DD*QT_S + DD*KT_S + BN*DD + BN*PS_S)

__global__ __launch_bounds__(256, 1)
void attn_kernel(const float* __restrict__ qr, const float* __restrict__ kr,
                 const float* __restrict__ v, float* __restrict__ out) {
    extern __shared__ float sm[];
    float* Qt = sm;                    // [128][66]  Qt[d][m]
    float* Kt = Qt + DD * QT_S;        // [128][65]  Kt[d][j]
    float* Vs = Kt + DD * KT_S;        // [64][128]  Vs[j][d]
    float* Ps = Vs + BN * DD;          // [64][66]   Ps[j][m]

    int qb = 31 - (int)blockIdx.x;     // heavy blocks first
    int bh = blockIdx.y;
    int tid = threadIdx.x;
    int tx = tid & 15, ty = tid >> 4;
    const float inv_sqrt_d = 0.08838834764831845f;

    const float* qbase = qr + ((size_t)bh * SS + (size_t)qb * BM) * DD;
    const float* kbase = kr + (size_t)bh * SS * DD;
    const float* vbase = v  + (size_t)bh * SS * DD;

    // Load Q transposed
    for (int i = tid; i < BM * 32; i += 256) {
        int r = i >> 5, d4 = i & 31;
        float4 val = *(const float4*)(qbase + (size_t)r * DD + d4 * 4);
        Qt[(4*d4+0)*QT_S + r] = val.x;
        Qt[(4*d4+1)*QT_S + r] = val.y;
        Qt[(4*d4+2)*QT_S + r] = val.z;
        Qt[(4*d4+3)*QT_S + r] = val.w;
    }

    float o[4][8];
    #pragma unroll
    for (int r = 0; r < 4; r++)
        #pragma unroll
        for (int c = 0; c < 8; c++) o[r][c] = 0.0f;
    float m_run[4], l_run[4];
    #pragma unroll
    for (int r = 0; r < 4; r++) { m_run[r] = -INFINITY; l_run[r] = 0.0f; }

    int ntiles = qb + 1;
    for (int t = 0; t < ntiles; t++) {
        __syncthreads();
        // Load K tile (transposed) and V tile
        const float* kt = kbase + (size_t)t * BN * DD;
        const float* vt = vbase + (size_t)t * BN * DD;
        for (int i = tid; i < BN * 32; i += 256) {
            int r = i >> 5, d4 = i & 31;
            float4 val = *(const float4*)(kt + (size_t)r * DD + d4 * 4);
            Kt[(4*d4+0)*KT_S + r] = val.x;
            Kt[(4*d4+1)*KT_S + r] = val.y;
            Kt[(4*d4+2)*KT_S + r] = val.z;
            Kt[(4*d4+3)*KT_S + r] = val.w;
        }
        for (int i = tid; i < BN * 32; i += 256)
            ((float4*)Vs)[i] = ((const float4*)vt)[i];
        __syncthreads();

        // QK^T
        float s_[4][4];
        #pragma unroll
        for (int r = 0; r < 4; r++)
            #pragma unroll
            for (int c = 0; c < 4; c++) s_[r][c] = 0.0f;

        #pragma unroll 8
        for (int d = 0; d < DD; d++) {
            float2 qa = *(float2*)&Qt[d * QT_S + ty * 4];
            float2 qb2 = *(float2*)&Qt[d * QT_S + ty * 4 + 2];
            float qv[4] = {qa.x, qa.y, qb2.x, qb2.y};
            float kv[4];
            #pragma unroll
            for (int c = 0; c < 4; c++) kv[c] = Kt[d * KT_S + tx + 16 * c];
            #pragma unroll
            for (int r = 0; r < 4; r++)
                #pragma unroll
                for (int c = 0; c < 4; c++)
                    s_[r][c] += qv[r] * kv[c];
        }

        // Scale + causal mask + online softmax
        bool diag = (t == qb);
        float rowmax[4];
        #pragma unroll
        for (int r = 0; r < 4; r++) {
            rowmax[r] = -INFINITY;
            #pragma unroll
            for (int c = 0; c < 4; c++) {
                float sv = s_[r][c] * inv_sqrt_d;
                if (diag && (tx + 16 * c) > (ty * 4 + r)) sv = -INFINITY;
                s_[r][c] = sv;
                rowmax[r] = fmaxf(rowmax[r], sv);
            }
        }
        #pragma unroll
        for (int r = 0; r < 4; r++) {
            #pragma unroll
            for (int off = 8; off >= 1; off >>= 1)
                rowmax[r] = fmaxf(rowmax[r], __shfl_xor_sync(0xffffffffu, rowmax[r], off, 16));
        }
        float newm[4], alpha[4], psum[4];
        #pragma unroll
        for (int r = 0; r < 4; r++) {
            newm[r] = fmaxf(m_run[r], rowmax[r]);
            alpha[r] = expf(m_run[r] - newm[r]);
            psum[r] = 0.0f;
            #pragma unroll
            for (int c = 0; c < 4; c++) {
                float p = expf(s_[r][c] - newm[r]);
                s_[r][c] = p;
                psum[r] += p;
            }
        }
        #pragma unroll
        for (int r = 0; r < 4; r++) {
            #pragma unroll
            for (int off = 8; off >= 1; off >>= 1)
                psum[r] += __shfl_xor_sync(0xffffffffu, psum[r], off, 16);
            l_run[r] = l_run[r] * alpha[r] + psum[r];
            m_run[r] = newm[r];
            #pragma unroll
            for (int c = 0; c < 8; c++) o[r][c] *= alpha[r];
        }
        // Write P
        #pragma unroll
        for (int r = 0; r < 4; r++)
            #pragma unroll
            for (int c = 0; c < 4; c++)
                Ps[(tx + 16 * c) * PS_S + ty * 4 + r] = s_[r][c];
        __syncthreads();

        // P @ V
        #pragma unroll 4
        for (int j = 0; j < BN; j++) {
            float2 pa = *(float2*)&Ps[j * PS_S + ty * 4];
            float2 pb = *(float2*)&Ps[j * PS_S + ty * 4 + 2];
            float pv[4] = {pa.x, pa.y, pb.x, pb.y};
            float4 v0 = *(float4*)&Vs[j * DD + tx * 8];
            float4 v1 = *(float4*)&Vs[j * DD + tx * 8 + 4];
            #pragma unroll
            for (int r = 0; r < 4; r++) {
                o[r][0] += pv[r] * v0.x; o[r][1] += pv[r] * v0.y;
                o[r][2] += pv[r] * v0.z; o[r][3] += pv[r] * v0.w;
                o[r][4] += pv[r] * v1.x; o[r][5] += pv[r] * v1.y;
                o[r][6] += pv[r] * v1.z; o[r][7] += pv[r] * v1.w;
            }
        }
    }

    // Epilogue
    #pragma unroll
    for (int r = 0; r < 4; r++) {
        float invl = 1.0f / l_run[r];
        size_t row = (size_t)bh * SS + (size_t)qb * BM + ty * 4 + r;
        float4 o0 = {o[r][0]*invl, o[r][1]*invl, o[r][2]*invl, o[r][3]*invl};
        float4 o1 = {o[r][4]*invl, o[r][5]*invl, o[r][6]*invl, o[r][7]*invl};
        *(float4*)&out[OFF_ATTN + row * DD + tx * 8]     = o0;
        *(float4*)&out[OFF_ATTN + row * DD + tx * 8 + 4] = o1;
    }
}

// ---------------------------------------------------------------------------
// K side: per (b,h,d) channel, top-17 over seq (s>=4), abs desc / idx asc ties.
// absmax of dense = 17th largest. Then quantize with outliers+sinks zeroed.
// ---------------------------------------------------------------------------
__global__ void kquant_kernel(const float* __restrict__ kr, float* __restrict__ out) {
    __shared__ unsigned mask[128 * 64];   // bitmap [d][s/32]
    int bh = blockIdx.x;
    int d = threadIdx.x;
    const float* base = kr + (size_t)bh * SS * DD + d;

    float absv[17]; int idxs[17]; float vals[17];
    #pragma unroll
    for (int i = 0; i < 17; i++) { absv[i] = -1.0f; idxs[i] = 0; vals[i] = 0.0f; }

    for (int s = 4; s < SS; s++) {
        float vv = base[(size_t)s * DD];
        float a = fabsf(vv);
        if (a > absv[16]) {
            int p = 16;
            while (p > 0 && absv[p-1] < a) {
                absv[p] = absv[p-1]; idxs[p] = idxs[p-1]; vals[p] = vals[p-1];
                p--;
            }
            absv[p] = a; idxs[p] = s; vals[p] = vv;
        }
    }

    float absmax = absv[16];
    float scale = fmaxf(absmax, 1e-8f) / 127.0f;

    size_t sp = ((size_t)bh * DD + d) * 16;
    for (int i = 0; i < 16; i++) {
        out[OFF_KSPV + sp + i] = vals[i];
        out[OFF_KSPI + sp + i] = (float)idxs[i];
    }
    out[OFF_KSCALE + (size_t)bh * DD + d] = scale;

    unsigned* m = mask + d * 64;
    for (int w = 0; w < 64; w++) m[w] = 0u;
    for (int i = 0; i < 16; i++) m[idxs[i] >> 5] |= (1u << (idxs[i] & 31));

    float* qout = out + OFF_KQ + (size_t)bh * SS * DD + d;
    for (int s = 0; s < SS; s++) {
        float vv = base[(size_t)s * DD];
        float q;
        if (s < 4 || ((m[s >> 5] >> (s & 31)) & 1u)) {
            q = 0.0f;
        } else {
            q = rintf(vv / scale);
            q = fminf(fmaxf(q, -127.0f), 127.0f);
        }
        qout[(size_t)s * DD] = q;
    }
}

// ---------------------------------------------------------------------------
// V side: warp per token. top-5 of |v| over D=128 (abs desc, idx asc ties).
// Outliers = first 4, absmax = 5th. Sinks (s<4): fully zeroed rows.
// ---------------------------------------------------------------------------
__global__ void vquant_kernel(const float* __restrict__ v, float* __restrict__ out) {
    int gwarp = (int)((blockIdx.x * (size_t)blockDim.x + threadIdx.x) >> 5);
    int lane = threadIdx.x & 31;
    if (gwarp >= BHN * SS) return;
    int s = gwarp & (SS - 1);

    const float* row = v + (size_t)gwarp * DD;
    float4 x = *(const float4*)(row + lane * 4);
    float vals[4] = {x.x, x.y, x.z, x.w};

    int tidx[4] = {0, 1, 2, 3};
    float tval[4] = {0.0f, 0.0f, 0.0f, 0.0f};
    float absmax = 0.0f;
    bool sink = (s < 4);

    if (!sink) {
        unsigned used = 0u;
        unsigned long long keys[4];
        #pragma unroll
        for (int i = 0; i < 4; i++) {
            unsigned ab = __float_as_uint(fabsf(vals[i]));
            keys[i] = ((unsigned long long)ab << 32) | (unsigned)(127 - (lane * 4 + i));
        }
        for (int rnd = 0; rnd < 5; rnd++) {
            unsigned long long best = 0ull;
            #pragma unroll
            for (int i = 0; i < 4; i++)
                if (!((used >> i) & 1u) && keys[i] > best) best = keys[i];
            #pragma unroll
            for (int off = 16; off >= 1; off >>= 1) {
                unsigned long long o2 = __shfl_xor_sync(0xffffffffu, best, off);
                if (o2 > best) best = o2;
            }
            int gidx = 127 - (int)(unsigned)(best & 0xffffffffull);
            float ab = __uint_as_float((unsigned)(best >> 32));
            int owner = gidx >> 2, slot = gidx & 3;
            if (lane == owner) used |= (1u << slot);
            if (rnd < 4) {
                float cand = (slot == 0) ? vals[0] : (slot == 1) ? vals[1]
                           : (slot == 2) ? vals[2] : vals[3];
                float sv = __shfl_sync(0xffffffffu, cand, owner);
                tidx[rnd] = gidx;
                tval[rnd] = sv;
            } else {
                absmax = ab;
            }
        }
    }

    float scale = fmaxf(absmax, 1e-8f) / 127.0f;

    float q[4];
    #pragma unroll
    for (int i = 0; i < 4; i++) {
        int gi = lane * 4 + i;
        bool zero = sink | (gi == tidx[0]) | (gi == tidx[1]) | (gi == tidx[2]) | (gi == tidx[3]);
        if (zero) {
            q[i] = 0.0f;
        } else {
            float r = rintf(vals[i] / scale);
            q[i] = fminf(fmaxf(r, -127.0f), 127.0f);
        }
    }
    float4 qo = {q[0], q[1], q[2], q[3]};
    *(float4*)&out[OFF_VQ + (size_t)gwarp * DD + lane * 4] = qo;

    if (lane == 0) {
        out[OFF_VSCALE + gwarp] = scale;
        #pragma unroll
        for (int t = 0; t < 4; t++) {
            out[OFF_VSPV + (size_t)gwarp * 4 + t] = tval[t];
            out[OFF_VSPI + (size_t)gwarp * 4 + t] = (float)tidx[t];
        }
    }
}

// ---------------------------------------------------------------------------
extern "C" void kernel_launch(void* const* d_in, const int* in_sizes, int n_in,
                              void* d_out, int out_size) {
    const float* q = (const float*)d_in[0];
    const float* k = (const float*)d_in[1];
    const float* v = (const float*)d_in[2];
    const int* pos = (const int*)d_in[3];
    float* out = (float*)d_out;

    float* qrot; cudaGetSymbolAddress((void**)&qrot, g_qrot);
    float* krot; cudaGetSymbolAddress((void**)&krot, g_krot);

    // 1. RoPE tables (double precision for f32 bit-fidelity)
    table_kernel<<<SS, 64>>>();

    // 2. RoPE
    {
        size_t n = (size_t)BB * HH * SS * DD;
        int threads = 256;
        int blocks = (int)((n + threads - 1) / threads);
        rope_kernel<<<blocks, threads>>>(q, k, pos);
    }

    // 3. Attention
    {
        size_t smem = (size_t)ATTN_SMEM_FLOATS * sizeof(float);
        cudaFuncSetAttribute(attn_kernel, cudaFuncAttributeMaxDynamicSharedMemorySize, (int)smem);
        dim3 grid(SS / BM, BHN);
        attn_kernel<<<grid, 256, smem>>>(qrot, krot, v, out);
    }

    // 4. K quant + outliers
    kquant_kernel<<<BHN, 128>>>(krot, out);

    // 5. V quant + outliers
    {
        int warps = BHN * SS;                 // 131072 tokens
        int threads = 256;
        int blocks = (warps * 32 + threads - 1) / threads;
        vquant_kernel<<<blocks, threads>>>(v, out);
    }
}

// round 8
// speedup vs baseline: 1.2880x; 1.2880x over previous
#include <cuda_runtime.h>
#include <cuda_bf16.h>
#include <math.h>
#include <stdint.h>

// Problem dims
#define BB 2
#define HH 32
#define SS 2048
#define DD 128
#define BHN (BB*HH)

// Output layout (floats), concatenated in reference return order
#define OFF_ATTN   ((size_t)0)
#define OFF_KQ     ((size_t)16777216)
#define OFF_KSCALE ((size_t)33554432)
#define OFF_VQ     ((size_t)33562624)
#define OFF_VSCALE ((size_t)50339840)
#define OFF_KSPV   ((size_t)50470912)
#define OFF_KSPI   ((size_t)50601984)
#define OFF_VSPV   ((size_t)50733056)
#define OFF_VSPI   ((size_t)51257344)

// Scratch (device globals: no allocation allowed)
__device__ float g_krot[BB*HH*SS*DD];
__device__ float g_cos[SS*64];
__device__ float g_sin[SS*64];
// Split-bf16 planes, pre-swizzled rows of 256B (16 x 16B chunks, chunk ^= row&7)
__device__ uint4 g_qh[BHN*SS*16];
__device__ uint4 g_ql[BHN*SS*16];
__device__ uint4 g_kh[BHN*SS*16];
__device__ uint4 g_kl[BHN*SS*16];
__device__ uint4 g_vh[BHN*SS*16];
__device__ uint4 g_vl[BHN*SS*16];

// ===========================================================================
// helpers
// ===========================================================================
__device__ __forceinline__ uint32_t smem_u32(const void* p) {
    uint32_t a;
    asm("{ .reg .u64 t; cvta.to.shared.u64 t, %1; cvt.u32.u64 %0, t; }"
        : "=r"(a) : "l"(p));
    return a;
}

// swizzled byte offset within a [rows][128 bf16] tile, 256B row pitch
__device__ __forceinline__ int soff(int r, int d) {
    return r * 256 + ((((d >> 3) ^ (r & 7)) & 15) << 4) + ((d & 7) << 1);
}

#define LDSM4(r, a) \
    asm volatile("ldmatrix.sync.aligned.m8n8.x4.shared.b16 {%0,%1,%2,%3}, [%4];" \
        : "=r"((r)[0]), "=r"((r)[1]), "=r"((r)[2]), "=r"((r)[3]) : "r"(a))
#define LDSM4T(r, a) \
    asm volatile("ldmatrix.sync.aligned.m8n8.x4.trans.shared.b16 {%0,%1,%2,%3}, [%4];" \
        : "=r"((r)[0]), "=r"((r)[1]), "=r"((r)[2]), "=r"((r)[3]) : "r"(a))

#define MMA16816(c, a0,a1,a2,a3, b0,b1) \
    asm volatile("mma.sync.aligned.m16n8k16.row.col.f32.bf16.bf16.f32 " \
        "{%0,%1,%2,%3}, {%4,%5,%6,%7}, {%8,%9}, {%0,%1,%2,%3};" \
        : "+f"((c)[0]), "+f"((c)[1]), "+f"((c)[2]), "+f"((c)[3]) \
        : "r"(a0), "r"(a1), "r"(a2), "r"(a3), "r"(b0), "r"(b1))

__device__ __forceinline__ float ex2f(float x) {
    float y;
    asm("ex2.approx.f32 %0, %1;" : "=f"(y) : "f"(x));
    return y;
}

// bf16 split: hi = bf16(a,b), lo = bf16(residuals). hi low half = a.
__device__ __forceinline__ uint32_t bsplit2(float a, float b, uint32_t& lo) {
    __nv_bfloat16 ha = __float2bfloat16_rn(a);
    __nv_bfloat16 hb = __float2bfloat16_rn(b);
    float ra = a - __bfloat162float(ha);
    float rb = b - __bfloat162float(hb);
    __nv_bfloat16 la = __float2bfloat16_rn(ra);
    __nv_bfloat16 lb = __float2bfloat16_rn(rb);
    lo = ((uint32_t)__bfloat16_as_ushort(lb) << 16) | (uint32_t)__bfloat16_as_ushort(la);
    return ((uint32_t)__bfloat16_as_ushort(hb) << 16) | (uint32_t)__bfloat16_as_ushort(ha);
}

__device__ __forceinline__ void split8(const float* v, uint4& hi, uint4& lo) {
    uint32_t l0, l1, l2, l3;
    hi.x = bsplit2(v[0], v[1], l0);
    hi.y = bsplit2(v[2], v[3], l1);
    hi.z = bsplit2(v[4], v[5], l2);
    hi.w = bsplit2(v[6], v[7], l3);
    lo.x = l0; lo.y = l1; lo.z = l2; lo.w = l3;
}

// ---------------------------------------------------------------------------
// RoPE cos/sin table (double precision for f32 bit-fidelity)
// ---------------------------------------------------------------------------
__global__ void table_kernel() {
    int s = blockIdx.x;
    int j = threadIdx.x;
    double e = (double)(2 * j) / 128.0;
    double p = pow(10000.0, e);
    float pf = (float)p;
    float invf = 1.0f / pf;
    float ang = __fmul_rn((float)s, invf);
    g_cos[s * 64 + j] = (float)cos((double)ang);
    g_sin[s * 64 + j] = (float)sin((double)ang);
}

// ---------------------------------------------------------------------------
// Fused RoPE + split-bf16 planes. One thread = one 8-elem lower chunk + its
// upper partner (d0 and d0+64). Writes krot f32 (for kquant) + qh/ql/kh/kl.
// ---------------------------------------------------------------------------
__global__ void rope_split_kernel(const float* __restrict__ q, const float* __restrict__ k,
                                  const int* __restrict__ pos_ids) {
    int idx = blockIdx.x * 256 + threadIdx.x;
    if (idx >= BHN * SS * 8) return;
    int c = idx & 7;
    int s = (idx >> 3) & 2047;
    int bh = idx >> 14;
    int b = bh >> 5;
    int pos = pos_ids[b * SS + s];
    int d0 = c * 8;
    size_t rb = ((size_t)bh * SS + s) * DD;

    float xq[8], yq[8], xk[8], yk[8], cs[8], sn[8];
    *(float4*)&xq[0] = *(const float4*)&q[rb + d0];
    *(float4*)&xq[4] = *(const float4*)&q[rb + d0 + 4];
    *(float4*)&yq[0] = *(const float4*)&q[rb + d0 + 64];
    *(float4*)&yq[4] = *(const float4*)&q[rb + d0 + 68];
    *(float4*)&xk[0] = *(const float4*)&k[rb + d0];
    *(float4*)&xk[4] = *(const float4*)&k[rb + d0 + 4];
    *(float4*)&yk[0] = *(const float4*)&k[rb + d0 + 64];
    *(float4*)&yk[4] = *(const float4*)&k[rb + d0 + 68];
    #pragma unroll
    for (int i = 0; i < 8; i++) {
        cs[i] = g_cos[pos * 64 + d0 + i];
        sn[i] = g_sin[pos * 64 + d0 + i];
    }

    float loq[8], upq[8], lok[8], upk[8];
    #pragma unroll
    for (int i = 0; i < 8; i++) {
        loq[i] = __fsub_rn(__fmul_rn(xq[i], cs[i]), __fmul_rn(yq[i], sn[i]));
        upq[i] = __fadd_rn(__fmul_rn(yq[i], cs[i]), __fmul_rn(xq[i], sn[i]));
        lok[i] = __fsub_rn(__fmul_rn(xk[i], cs[i]), __fmul_rn(yk[i], sn[i]));
        upk[i] = __fadd_rn(__fmul_rn(yk[i], cs[i]), __fmul_rn(xk[i], sn[i]));
    }

    // krot f32 (natural layout) for kquant
    *(float4*)&g_krot[rb + d0]      = *(float4*)&lok[0];
    *(float4*)&g_krot[rb + d0 + 4]  = *(float4*)&lok[4];
    *(float4*)&g_krot[rb + d0 + 64] = *(float4*)&upk[0];
    *(float4*)&g_krot[rb + d0 + 68] = *(float4*)&upk[4];

    // split planes (pre-swizzled chunks)
    size_t rowb = ((size_t)bh * SS + s) * 16;
    int pcl = c ^ (s & 7);
    int pcu = 8 + pcl;
    uint4 hi, lo;
    split8(loq, hi, lo); g_qh[rowb + pcl] = hi; g_ql[rowb + pcl] = lo;
    split8(upq, hi, lo); g_qh[rowb + pcu] = hi; g_ql[rowb + pcu] = lo;
    split8(lok, hi, lo); g_kh[rowb + pcl] = hi; g_kl[rowb + pcl] = lo;
    split8(upk, hi, lo); g_kh[rowb + pcu] = hi; g_kl[rowb + pcu] = lo;
}

// ---------------------------------------------------------------------------
// V split planes (no rope). One thread = one 8-elem chunk.
// ---------------------------------------------------------------------------
__global__ void v_split_kernel(const float* __restrict__ v) {
    int idx = blockIdx.x * 256 + threadIdx.x;
    if (idx >= BHN * SS * 16) return;
    int c = idx & 15;
    int s = (idx >> 4) & 2047;
    int bh = idx >> 15;
    size_t rb = ((size_t)bh * SS + s) * DD;
    float x[8];
    *(float4*)&x[0] = *(const float4*)&v[rb + c * 8];
    *(float4*)&x[4] = *(const float4*)&v[rb + c * 8 + 4];
    uint4 hi, lo;
    split8(x, hi, lo);
    size_t rowb = ((size_t)bh * SS + s) * 16;
    int pc = c ^ (s & 7);
    g_vh[rowb + pc] = hi;
    g_vl[rowb + pc] = lo;
}

// ---------------------------------------------------------------------------
// Flash attention via mma.sync m16n8k16 bf16 (3-pass split), no-rescale softmax.
// 8 warps, BM=128 (16 rows/warp), BN=64. P stays in registers (frag reuse).
// Smem: QH 0, QL 32K, KH 64K, KL 80K, VH 96K, VL 112K => 128KB.
// ---------------------------------------------------------------------------
#define SMQ_L 32768
#define SMK_H 65536
#define SMK_L 81920
#define SMV_H 98304
#define SMV_L 114688
#define SM_TOT 131072

__global__ __launch_bounds__(256, 1)
void attn_mma_kernel(const uint4* __restrict__ pqh, const uint4* __restrict__ pql,
                     const uint4* __restrict__ pkh, const uint4* __restrict__ pkl,
                     const uint4* __restrict__ pvh, const uint4* __restrict__ pvl,
                     float* __restrict__ out) {
    extern __shared__ char smc[];
    const int tid = threadIdx.x;
    const int w = tid >> 5, l = tid & 31;
    const int qb = 15 - (int)blockIdx.x;     // heavy blocks first
    const int bh = blockIdx.y;
    const uint32_t sb = smem_u32(smc);

    // Q tile copy (linear: planes are pre-swizzled)
    {
        size_t src = ((size_t)bh * SS + (size_t)qb * 128) * 16;
        uint4* dh = (uint4*)smc;
        uint4* dl = (uint4*)(smc + SMQ_L);
        for (int i = tid; i < 2048; i += 256) { dh[i] = pqh[src + i]; dl[i] = pql[src + i]; }
    }

    float o_[16][4];
    #pragma unroll
    for (int i = 0; i < 16; i++)
        #pragma unroll
        for (int j = 0; j < 4; j++) o_[i][j] = 0.0f;
    float lsum0 = 0.0f, lsum1 = 0.0f;

    const int rowmin = qb * 128 + w * 16;
    const int row0 = rowmin + (l >> 2);
    const int aR = ((l >> 3) & 1) * 8 + (l & 7);
    const int aK = ((l >> 4) & 1) * 8;
    const int bR = ((l >> 4) & 1) * 8 + (l & 7);
    const int bK = ((l >> 3) & 1) * 8;
    const float sc = 0.088388347648318447f * 1.4426950408889634f;  // 1/sqrt(128)*log2(e)

    const int nt = 2 * (qb + 1);
    for (int t = 0; t < nt; t++) {
        if (t) __syncthreads();
        {   // K/V tile copy (linear)
            size_t src = ((size_t)bh * SS + (size_t)t * 64) * 16;
            uint4* dkh = (uint4*)(smc + SMK_H);
            uint4* dkl = (uint4*)(smc + SMK_L);
            uint4* dvh = (uint4*)(smc + SMV_H);
            uint4* dvl = (uint4*)(smc + SMV_L);
            for (int i = tid; i < 1024; i += 256) {
                dkh[i] = pkh[src + i];
                dkl[i] = pkl[src + i];
                dvh[i] = pvh[src + i];
                dvl[i] = pvl[src + i];
            }
        }
        __syncthreads();
        if (64 * t > rowmin + 15) continue;   // whole tile above diagonal for this warp

        // ---- S = Qhi*Khi + Qlo*Khi + Qhi*Klo ----
        float s_[8][4];
        #pragma unroll
        for (int i = 0; i < 8; i++)
            #pragma unroll
            for (int j = 0; j < 4; j++) s_[i][j] = 0.0f;

        #pragma unroll
        for (int ks = 0; ks < 8; ks++) {
            uint32_t qh_[4], ql_[4];
            uint32_t aaddr = sb + soff(w * 16 + aR, ks * 16 + aK);
            LDSM4(qh_, aaddr);
            LDSM4(ql_, aaddr + SMQ_L);
            #pragma unroll
            for (int n0 = 0; n0 < 4; n0++) {
                uint32_t kh_[4], kl_[4];
                uint32_t baddr = sb + SMK_H + soff(n0 * 16 + bR, ks * 16 + bK);
                LDSM4(kh_, baddr);
                LDSM4(kl_, baddr + (SMK_L - SMK_H));
                MMA16816(s_[2*n0],   qh_[0],qh_[1],qh_[2],qh_[3], kh_[0], kh_[1]);
                MMA16816(s_[2*n0],   ql_[0],ql_[1],ql_[2],ql_[3], kh_[0], kh_[1]);
                MMA16816(s_[2*n0],   qh_[0],qh_[1],qh_[2],qh_[3], kl_[0], kl_[1]);
                MMA16816(s_[2*n0+1], qh_[0],qh_[1],qh_[2],qh_[3], kh_[2], kh_[3]);
                MMA16816(s_[2*n0+1], ql_[0],ql_[1],ql_[2],ql_[3], kh_[2], kh_[3]);
                MMA16816(s_[2*n0+1], qh_[0],qh_[1],qh_[2],qh_[3], kl_[2], kl_[3]);
            }
        }

        // ---- softmax (no rescale), build P fragments in regs ----
        const bool needmask = (64 * t + 63 > rowmin);
        uint32_t phi[8][2], plo[8][2];
        const int colb = 64 * t + 2 * (l & 3);
        #pragma unroll
        for (int n2 = 0; n2 < 8; n2++) {
            float p0 = ex2f(s_[n2][0] * sc);
            float p1 = ex2f(s_[n2][1] * sc);
            float p2 = ex2f(s_[n2][2] * sc);
            float p3 = ex2f(s_[n2][3] * sc);
            if (needmask) {
                int c0 = colb + 8 * n2;
                if (c0     > row0)     p0 = 0.0f;
                if (c0 + 1 > row0)     p1 = 0.0f;
                if (c0     > row0 + 8) p2 = 0.0f;
                if (c0 + 1 > row0 + 8) p3 = 0.0f;
            }
            lsum0 += p0 + p1;
            lsum1 += p2 + p3;
            uint32_t t0, t1;
            phi[n2][0] = bsplit2(p0, p1, t0); plo[n2][0] = t0;
            phi[n2][1] = bsplit2(p2, p3, t1); plo[n2][1] = t1;
        }

        // ---- O += Phi*Vhi + Plo*Vhi + Phi*Vlo ----
        const int vR = ((l >> 3) & 1) * 8 + (l & 7);
        const int vD = ((l >> 4) & 1) * 8;
        #pragma unroll
        for (int ks = 0; ks < 4; ks++) {
            uint32_t A0 = phi[2*ks][0], A1 = phi[2*ks][1];
            uint32_t A2 = phi[2*ks+1][0], A3 = phi[2*ks+1][1];
            uint32_t L0 = plo[2*ks][0], L1 = plo[2*ks][1];
            uint32_t L2 = plo[2*ks+1][0], L3 = plo[2*ks+1][1];
            #pragma unroll
            for (int d0 = 0; d0 < 8; d0++) {
                uint32_t vh_[4], vl_[4];
                uint32_t vaddr = sb + SMV_H + soff(ks * 16 + vR, d0 * 16 + vD);
                LDSM4T(vh_, vaddr);
                LDSM4T(vl_, vaddr + (SMV_L - SMV_H));
                MMA16816(o_[2*d0],   A0,A1,A2,A3, vh_[0], vh_[1]);
                MMA16816(o_[2*d0],   L0,L1,L2,L3, vh_[0], vh_[1]);
                MMA16816(o_[2*d0],   A0,A1,A2,A3, vl_[0], vl_[1]);
                MMA16816(o_[2*d0+1], A0,A1,A2,A3, vh_[2], vh_[3]);
                MMA16816(o_[2*d0+1], L0,L1,L2,L3, vh_[2], vh_[3]);
                MMA16816(o_[2*d0+1], A0,A1,A2,A3, vl_[2], vl_[3]);
            }
        }
    }

    // ---- epilogue: reduce l over quad, normalize, store ----
    lsum0 += __shfl_xor_sync(0xffffffffu, lsum0, 1);
    lsum0 += __shfl_xor_sync(0xffffffffu, lsum0, 2);
    lsum1 += __shfl_xor_sync(0xffffffffu, lsum1, 1);
    lsum1 += __shfl_xor_sync(0xffffffffu, lsum1, 2);
    float inv0 = 1.0f / lsum0;
    float inv1 = 1.0f / lsum1;
    size_t rbase = OFF_ATTN + ((size_t)bh * SS + row0) * DD;
    #pragma unroll
    for (int n2 = 0; n2 < 16; n2++) {
        int d = n2 * 8 + 2 * (l & 3);
        float2 a = {o_[n2][0] * inv0, o_[n2][1] * inv0};
        float2 b = {o_[n2][2] * inv1, o_[n2][3] * inv1};
        *(float2*)&out[rbase + d] = a;
        *(float2*)&out[rbase + 8 * DD + d] = b;
    }
}

// ---------------------------------------------------------------------------
// K side: per (b,h,d) channel, top-17 over seq (s>=4), abs desc / idx asc ties.
// ---------------------------------------------------------------------------
__global__ void kquant_kernel(const float* __restrict__ kr, float* __restrict__ out) {
    __shared__ unsigned mask[128 * 64];
    int bh = blockIdx.x;
    int d = threadIdx.x;
    const float* base = kr + (size_t)bh * SS * DD + d;

    float absv[17]; int idxs[17]; float vals[17];
    #pragma unroll
    for (int i = 0; i < 17; i++) { absv[i] = -1.0f; idxs[i] = 0; vals[i] = 0.0f; }

    for (int s = 4; s < SS; s++) {
        float vv = base[(size_t)s * DD];
        float a = fabsf(vv);
        if (a > absv[16]) {
            int p = 16;
            while (p > 0 && absv[p-1] < a) {
                absv[p] = absv[p-1]; idxs[p] = idxs[p-1]; vals[p] = vals[p-1];
                p--;
            }
            absv[p] = a; idxs[p] = s; vals[p] = vv;
        }
    }

    float absmax = absv[16];
    float scale = fmaxf(absmax, 1e-8f) / 127.0f;

    size_t sp = ((size_t)bh * DD + d) * 16;
    for (int i = 0; i < 16; i++) {
        out[OFF_KSPV + sp + i] = vals[i];
        out[OFF_KSPI + sp + i] = (float)idxs[i];
    }
    out[OFF_KSCALE + (size_t)bh * DD + d] = scale;

    unsigned* m = mask + d * 64;
    for (int wd = 0; wd < 64; wd++) m[wd] = 0u;
    for (int i = 0; i < 16; i++) m[idxs[i] >> 5] |= (1u << (idxs[i] & 31));

    float* qout = out + OFF_KQ + (size_t)bh * SS * DD + d;
    for (int s = 0; s < SS; s++) {
        float vv = base[(size_t)s * DD];
        float q;
        if (s < 4 || ((m[s >> 5] >> (s & 31)) & 1u)) {
            q = 0.0f;
        } else {
            q = rintf(vv / scale);
            q = fminf(fmaxf(q, -127.0f), 127.0f);
        }
        qout[(size_t)s * DD] = q;
    }
}

// ---------------------------------------------------------------------------
// V side: warp per token. top-5 of |v| over D=128 (abs desc, idx asc ties).
// ---------------------------------------------------------------------------
__global__ void vquant_kernel(const float* __restrict__ v, float* __restrict__ out) {
    int gwarp = (int)((blockIdx.x * (size_t)blockDim.x + threadIdx.x) >> 5);
    int lane = threadIdx.x & 31;
    if (gwarp >= BHN * SS) return;
    int s = gwarp & (SS - 1);

    const float* row = v + (size_t)gwarp * DD;
    float4 x = *(const float4*)(row + lane * 4);
    float vals[4] = {x.x, x.y, x.z, x.w};

    int tidx[4] = {0, 1, 2, 3};
    float tval[4] = {0.0f, 0.0f, 0.0f, 0.0f};
    float absmax = 0.0f;
    bool sink = (s < 4);

    if (!sink) {
        unsigned used = 0u;
        unsigned long long keys[4];
        #pragma unroll
        for (int i = 0; i < 4; i++) {
            unsigned ab = __float_as_uint(fabsf(vals[i]));
            keys[i] = ((unsigned long long)ab << 32) | (unsigned)(127 - (lane * 4 + i));
        }
        for (int rnd = 0; rnd < 5; rnd++) {
            unsigned long long best = 0ull;
            #pragma unroll
            for (int i = 0; i < 4; i++)
                if (!((used >> i) & 1u) && keys[i] > best) best = keys[i];
            #pragma unroll
            for (int off = 16; off >= 1; off >>= 1) {
                unsigned long long o2 = __shfl_xor_sync(0xffffffffu, best, off);
                if (o2 > best) best = o2;
            }
            int gidx = 127 - (int)(unsigned)(best & 0xffffffffull);
            float ab = __uint_as_float((unsigned)(best >> 32));
            int owner = gidx >> 2, slot = gidx & 3;
            if (lane == owner) used |= (1u << slot);
            if (rnd < 4) {
                float cand = (slot == 0) ? vals[0] : (slot == 1) ? vals[1]
                           : (slot == 2) ? vals[2] : vals[3];
                float sv = __shfl_sync(0xffffffffu, cand, owner);
                tidx[rnd] = gidx;
                tval[rnd] = sv;
            } else {
                absmax = ab;
            }
        }
    }

    float scale = fmaxf(absmax, 1e-8f) / 127.0f;

    float q[4];
    #pragma unroll
    for (int i = 0; i < 4; i++) {
        int gi = lane * 4 + i;
        bool zero = sink | (gi == tidx[0]) | (gi == tidx[1]) | (gi == tidx[2]) | (gi == tidx[3]);
        if (zero) {
            q[i] = 0.0f;
        } else {
            float r = rintf(vals[i] / scale);
            q[i] = fminf(fmaxf(r, -127.0f), 127.0f);
        }
    }
    float4 qo = {q[0], q[1], q[2], q[3]};
    *(float4*)&out[OFF_VQ + (size_t)gwarp * DD + lane * 4] = qo;

    if (lane == 0) {
        out[OFF_VSCALE + gwarp] = scale;
        #pragma unroll
        for (int t = 0; t < 4; t++) {
            out[OFF_VSPV + (size_t)gwarp * 4 + t] = tval[t];
            out[OFF_VSPI + (size_t)gwarp * 4 + t] = (float)tidx[t];
        }
    }
}

// ---------------------------------------------------------------------------
extern "C" void kernel_launch(void* const* d_in, const int* in_sizes, int n_in,
                              void* d_out, int out_size) {
    const float* q = (const float*)d_in[0];
    const float* k = (const float*)d_in[1];
    const float* v = (const float*)d_in[2];
    const int* pos = (const int*)d_in[3];
    float* out = (float*)d_out;

    float* krot; cudaGetSymbolAddress((void**)&krot, g_krot);
    uint4 *pqh, *pql, *pkh, *pkl, *pvh, *pvl;
    cudaGetSymbolAddress((void**)&pqh, g_qh);
    cudaGetSymbolAddress((void**)&pql, g_ql);
    cudaGetSymbolAddress((void**)&pkh, g_kh);
    cudaGetSymbolAddress((void**)&pkl, g_kl);
    cudaGetSymbolAddress((void**)&pvh, g_vh);
    cudaGetSymbolAddress((void**)&pvl, g_vl);

    // 1. RoPE tables
    table_kernel<<<SS, 64>>>();

    // 2. Fused RoPE + bf16 split planes (Q, K) + krot f32
    rope_split_kernel<<<(BHN * SS * 8 + 255) / 256, 256>>>(q, k, pos);

    // 3. V split planes
    v_split_kernel<<<(BHN * SS * 16 + 255) / 256, 256>>>(v);

    // 4. Attention (mma.sync bf16, 3-pass split)
    {
        cudaFuncSetAttribute(attn_mma_kernel, cudaFuncAttributeMaxDynamicSharedMemorySize, SM_TOT);
        dim3 grid(16, BHN);
        attn_mma_kernel<<<grid, 256, SM_TOT>>>(pqh, pql, pkh, pkl, pvh, pvl, out);
    }

    // 5. K quant + outliers
    kquant_kernel<<<BHN, 128>>>(krot, out);

    // 6. V quant + outliers
    {
        int warps = BHN * SS;
        int threads = 256;
        int blocks = (warps * 32 + threads - 1) / threads;
        vquant_kernel<<<blocks, threads>>>(v, out);
    }
}